// round 3
// baseline (speedup 1.0000x reference)
#include <cuda_runtime.h>
#include <math.h>

// CBOW negative-sampling loss.
//   d_in[0]: in_embed  float32 [100000, 128]
//   d_in[1]: out_embed float32 [100000, 128]
//   d_in[2]: context   int32   [B, 8]
//   d_in[3]: target    int32   [B]
//   d_in[4]: negatives int32   [B, 10]
// Output: float32 [B]
//
// One warp per element; lane l owns float4 chunk l of each 512B row.
// All 19 row loads issued back-to-back (MLP=19/warp); L2 evict_last bias
// via the createpolicy + L2::cache_hint form (bare evict_last on v4.f32
// is rejected by this ptxas).

#define CTX 8
#define NEG 10
#define D   128

__device__ __forceinline__ float4 ldg_evict_last(const float4* p) {
    float4 r;
    asm volatile(
        "{\n\t"
        ".reg .b64 pol;\n\t"
        "createpolicy.fractional.L2::evict_last.b64 pol, 1.0;\n\t"
        "ld.global.nc.L2::cache_hint.v4.f32 {%0,%1,%2,%3}, [%4], pol;\n\t"
        "}"
        : "=f"(r.x), "=f"(r.y), "=f"(r.z), "=f"(r.w)
        : "l"(p));
    return r;
}

__device__ __forceinline__ float log_sigmoid(float x) {
    return fminf(x, 0.0f) - log1pf(__expf(-fabsf(x)));
}

__global__ __launch_bounds__(256) void cbow_neg_kernel(
    const float* __restrict__ in_embed,
    const float* __restrict__ out_embed,
    const int*   __restrict__ context,
    const int*   __restrict__ target,
    const int*   __restrict__ negatives,
    float*       __restrict__ out,
    int B)
{
    const int warp = (blockIdx.x * blockDim.x + threadIdx.x) >> 5;
    const int lane = threadIdx.x & 31;
    if (warp >= B) return;

    // ---- 1) all index loads first (warp-uniform, L1 broadcast) ----
    int cidx[CTX], nidx[NEG], tidx;
    #pragma unroll
    for (int c = 0; c < CTX; c++) cidx[c] = __ldg(&context[warp * CTX + c]);
    tidx = __ldg(&target[warp]);
    #pragma unroll
    for (int k = 0; k < NEG; k++) nidx[k] = __ldg(&negatives[warp * NEG + k]);

    // ---- 2) issue ALL 19 row loads back-to-back (max MLP) ----
    float4 cvec[CTX];
    #pragma unroll
    for (int c = 0; c < CTX; c++)
        cvec[c] = ldg_evict_last(reinterpret_cast<const float4*>(
                      in_embed + (size_t)cidx[c] * D) + lane);

    float4 uvec[NEG + 1];
    uvec[0] = ldg_evict_last(reinterpret_cast<const float4*>(
                  out_embed + (size_t)tidx * D) + lane);
    #pragma unroll
    for (int k = 0; k < NEG; k++)
        uvec[1 + k] = ldg_evict_last(reinterpret_cast<const float4*>(
                          out_embed + (size_t)nidx[k] * D) + lane);

    // ---- 3) v = mean of context rows ----
    float4 v = cvec[0];
    #pragma unroll
    for (int c = 1; c < CTX; c++) {
        v.x += cvec[c].x; v.y += cvec[c].y; v.z += cvec[c].z; v.w += cvec[c].w;
    }
    const float inv = 1.0f / (float)CTX;
    v.x *= inv; v.y *= inv; v.z *= inv; v.w *= inv;

    // ---- 4) 11 per-lane partial dots ----
    float s[NEG + 1];
    #pragma unroll
    for (int i = 0; i < NEG + 1; i++)
        s[i] = v.x * uvec[i].x + v.y * uvec[i].y
             + v.z * uvec[i].z + v.w * uvec[i].w;

    // ---- 5) butterfly-reduce each score across the warp ----
    #pragma unroll
    for (int i = 0; i < NEG + 1; i++) {
        float x = s[i];
        x += __shfl_xor_sync(0xffffffffu, x, 16);
        x += __shfl_xor_sync(0xffffffffu, x, 8);
        x += __shfl_xor_sync(0xffffffffu, x, 4);
        x += __shfl_xor_sync(0xffffffffu, x, 2);
        x += __shfl_xor_sync(0xffffffffu, x, 1);
        s[i] = x;
    }

    // ---- 6) loss ----
    if (lane == 0) {
        float loss = -log_sigmoid(s[0]);
        #pragma unroll
        for (int k = 0; k < NEG; k++)
            loss -= log_sigmoid(-s[1 + k]);
        out[warp] = loss;
    }
}

extern "C" void kernel_launch(void* const* d_in, const int* in_sizes, int n_in,
                              void* d_out, int out_size)
{
    const float* in_embed  = (const float*)d_in[0];
    const float* out_embed = (const float*)d_in[1];
    const int*   context   = (const int*)d_in[2];
    const int*   target    = (const int*)d_in[3];
    const int*   negatives = (const int*)d_in[4];
    float*       out       = (float*)d_out;

    const int B = out_size;                 // 16384
    const int threads = 256;                // 8 warps/block
    const int blocks  = (B * 32 + threads - 1) / threads;
    cbow_neg_kernel<<<blocks, threads>>>(in_embed, out_embed, context, target,
                                         negatives, out, B);
}

// round 4
// speedup vs baseline: 1.0746x; 1.0746x over previous
#include <cuda_runtime.h>
#include <math.h>

// CBOW negative-sampling loss.
//   d_in[0]: in_embed  float32 [100000, 128]
//   d_in[1]: out_embed float32 [100000, 128]
//   d_in[2]: context   int32   [B, 8]
//   d_in[3]: target    int32   [B]
//   d_in[4]: negatives int32   [B, 10]
// Output: float32 [B]
//
// Round 4: 4 elements per warp (8-lane groups) to amortize warp-level work.
// Lane `sub` (0..7) of group g owns float4 slots {sub, sub+8, sub+16, sub+24}
// of each 512B row, so every warp LDG.128 reads 4x128B coalesced lines and
// serves 4 batch elements at once. Butterfly reduce is 3 stages instead of 5,
// and the 11 log-sigmoid epilogue runs on 4 group-leader lanes in parallel.

#define CTX 8
#define NEG 10
#define D   128

__device__ __forceinline__ float log_sigmoid_fast(float x) {
    // log(sigmoid(x)) = min(x,0) - log(1 + exp(-|x|));  MUFU-based, ~9 instrs
    return fminf(x, 0.0f) - __logf(1.0f + __expf(-fabsf(x)));
}

__device__ __forceinline__ float dot4(float4 a, float4 b) {
    return a.x * b.x + a.y * b.y + a.z * b.z + a.w * b.w;
}

__global__ __launch_bounds__(256) void cbow_neg_kernel(
    const float* __restrict__ in_embed,
    const float* __restrict__ out_embed,
    const int*   __restrict__ context,
    const int*   __restrict__ target,
    const int*   __restrict__ negatives,
    float*       __restrict__ out,
    int B)
{
    const int lane   = threadIdx.x & 31;
    const int warpId = (blockIdx.x * blockDim.x + threadIdx.x) >> 5;
    const int group  = lane >> 3;          // 0..3: which element in this warp
    const int sub    = lane & 7;           // 0..7: lane within group
    const int e      = warpId * 4 + group; // batch element
    if (e >= B) return;                    // B % 4 == 0, warp-uniform exit

    // ---- v = mean of 8 context rows; each lane holds 4 float4 slices ----
    float4 v0, v1, v2, v3;
    {
        const int idx0 = __ldg(&context[e * CTX]);
        const float4* r = reinterpret_cast<const float4*>(in_embed + (size_t)idx0 * D);
        v0 = __ldg(r + sub);
        v1 = __ldg(r + sub + 8);
        v2 = __ldg(r + sub + 16);
        v3 = __ldg(r + sub + 24);
    }
    #pragma unroll
    for (int c = 1; c < CTX; c++) {
        const int idx = __ldg(&context[e * CTX + c]);
        const float4* r = reinterpret_cast<const float4*>(in_embed + (size_t)idx * D);
        const float4 a = __ldg(r + sub);
        const float4 b = __ldg(r + sub + 8);
        const float4 cc = __ldg(r + sub + 16);
        const float4 d = __ldg(r + sub + 24);
        v0.x += a.x;  v0.y += a.y;  v0.z += a.z;  v0.w += a.w;
        v1.x += b.x;  v1.y += b.y;  v1.z += b.z;  v1.w += b.w;
        v2.x += cc.x; v2.y += cc.y; v2.z += cc.z; v2.w += cc.w;
        v3.x += d.x;  v3.y += d.y;  v3.z += d.z;  v3.w += d.w;
    }
    const float inv = 1.0f / (float)CTX;
    v0.x *= inv; v0.y *= inv; v0.z *= inv; v0.w *= inv;
    v1.x *= inv; v1.y *= inv; v1.z *= inv; v1.w *= inv;
    v2.x *= inv; v2.y *= inv; v2.z *= inv; v2.w *= inv;
    v3.x *= inv; v3.y *= inv; v3.z *= inv; v3.w *= inv;

    // ---- 11 per-lane partial dot products (target + 10 negatives) ----
    int ridx[NEG + 1];
    ridx[0] = __ldg(&target[e]);
    #pragma unroll
    for (int k = 0; k < NEG; k++) ridx[1 + k] = __ldg(&negatives[e * NEG + k]);

    float s[NEG + 1];
    #pragma unroll
    for (int i = 0; i < NEG + 1; i++) {
        const float4* u = reinterpret_cast<const float4*>(out_embed + (size_t)ridx[i] * D);
        const float4 a = __ldg(u + sub);
        const float4 b = __ldg(u + sub + 8);
        const float4 c = __ldg(u + sub + 16);
        const float4 d = __ldg(u + sub + 24);
        s[i] = dot4(v0, a) + dot4(v1, b) + dot4(v2, c) + dot4(v3, d);
    }

    // ---- reduce each score within the 8-lane group (3 butterfly stages) ----
    #pragma unroll
    for (int i = 0; i < NEG + 1; i++) {
        float x = s[i];
        x += __shfl_xor_sync(0xffffffffu, x, 4);
        x += __shfl_xor_sync(0xffffffffu, x, 2);
        x += __shfl_xor_sync(0xffffffffu, x, 1);
        s[i] = x;
    }

    // ---- epilogue: 4 group leaders run in parallel lanes ----
    if (sub == 0) {
        float acc = log_sigmoid_fast(s[0]);
        #pragma unroll
        for (int k = 0; k < NEG; k++)
            acc += log_sigmoid_fast(-s[1 + k]);
        out[e] = -acc;
    }
}

extern "C" void kernel_launch(void* const* d_in, const int* in_sizes, int n_in,
                              void* d_out, int out_size)
{
    const float* in_embed  = (const float*)d_in[0];
    const float* out_embed = (const float*)d_in[1];
    const int*   context   = (const int*)d_in[2];
    const int*   target    = (const int*)d_in[3];
    const int*   negatives = (const int*)d_in[4];
    float*       out       = (float*)d_out;

    const int B = out_size;                       // 16384
    const int warps = (B + 3) / 4;                // 4 elements per warp
    const int threads = 256;                      // 8 warps/block
    const int blocks = (warps * 32 + threads - 1) / threads;
    cbow_neg_kernel<<<blocks, threads>>>(in_embed, out_embed, context, target,
                                         negatives, out, B);
}

// round 5
// speedup vs baseline: 1.2478x; 1.1612x over previous
#include <cuda_runtime.h>
#include <math.h>

// CBOW negative-sampling loss.
//   d_in[0]: in_embed  float32 [100000, 128]
//   d_in[1]: out_embed float32 [100000, 128]
//   d_in[2]: context   int32   [B, 8]
//   d_in[3]: target    int32   [B]
//   d_in[4]: negatives int32   [B, 10]
// Output: float32 [B]
//
// Round 5: 2 elements per warp (16-lane groups), 128-thread blocks.
// Lane `sub` (0..15) of group g owns float4 slots {sub, sub+16} of each
// 512B row: every warp LDG.128 reads 4 coalesced 128B lines serving 2
// elements. Balances warp-work amortization (R4) against occupancy (R1):
// ~55 regs -> ~32 warps/SM, grid=2048 for fine-grained CTA balance.

#define CTX 8
#define NEG 10
#define D   128

__device__ __forceinline__ float log_sigmoid_fast(float x) {
    // log(sigmoid(x)) = min(x,0) - log(1 + exp(-|x|))
    return fminf(x, 0.0f) - __logf(1.0f + __expf(-fabsf(x)));
}

__device__ __forceinline__ float dot4(float4 a, float4 b) {
    return a.x * b.x + a.y * b.y + a.z * b.z + a.w * b.w;
}

__global__ __launch_bounds__(128) void cbow_neg_kernel(
    const float* __restrict__ in_embed,
    const float* __restrict__ out_embed,
    const int*   __restrict__ context,
    const int*   __restrict__ target,
    const int*   __restrict__ negatives,
    float*       __restrict__ out,
    int B)
{
    const int lane   = threadIdx.x & 31;
    const int warpId = (blockIdx.x * blockDim.x + threadIdx.x) >> 5;
    const int group  = lane >> 4;            // 0..1: element within warp
    const int sub    = lane & 15;            // 0..15: lane within group
    const int e      = warpId * 2 + group;   // batch element
    if (e >= B) return;                      // B even, warp-uniform exit

    // ---- all index loads first (L1-broadcast within each half-warp) ----
    int cidx[CTX];
    #pragma unroll
    for (int c = 0; c < CTX; c++) cidx[c] = __ldg(&context[e * CTX + c]);
    int ridx[NEG + 1];
    ridx[0] = __ldg(&target[e]);
    #pragma unroll
    for (int k = 0; k < NEG; k++) ridx[1 + k] = __ldg(&negatives[e * NEG + k]);

    // ---- v = mean of 8 context rows; lane holds slots {sub, sub+16} ----
    float4 v0, v1;
    {
        const float4* r = reinterpret_cast<const float4*>(
                              in_embed + (size_t)cidx[0] * D);
        v0 = __ldg(r + sub);
        v1 = __ldg(r + sub + 16);
    }
    #pragma unroll
    for (int c = 1; c < CTX; c++) {
        const float4* r = reinterpret_cast<const float4*>(
                              in_embed + (size_t)cidx[c] * D);
        const float4 a = __ldg(r + sub);
        const float4 b = __ldg(r + sub + 16);
        v0.x += a.x; v0.y += a.y; v0.z += a.z; v0.w += a.w;
        v1.x += b.x; v1.y += b.y; v1.z += b.z; v1.w += b.w;
    }
    const float inv = 1.0f / (float)CTX;
    v0.x *= inv; v0.y *= inv; v0.z *= inv; v0.w *= inv;
    v1.x *= inv; v1.y *= inv; v1.z *= inv; v1.w *= inv;

    // ---- 11 per-lane partial dots (target + 10 negatives) ----
    float s[NEG + 1];
    #pragma unroll
    for (int i = 0; i < NEG + 1; i++) {
        const float4* u = reinterpret_cast<const float4*>(
                              out_embed + (size_t)ridx[i] * D);
        const float4 a = __ldg(u + sub);
        const float4 b = __ldg(u + sub + 16);
        s[i] = dot4(v0, a) + dot4(v1, b);
    }

    // ---- reduce each score within the 16-lane group (4 stages) ----
    #pragma unroll
    for (int i = 0; i < NEG + 1; i++) {
        float x = s[i];
        x += __shfl_xor_sync(0xffffffffu, x, 8);
        x += __shfl_xor_sync(0xffffffffu, x, 4);
        x += __shfl_xor_sync(0xffffffffu, x, 2);
        x += __shfl_xor_sync(0xffffffffu, x, 1);
        s[i] = x;
    }

    // ---- epilogue: 2 group leaders per warp in parallel lanes ----
    if (sub == 0) {
        float acc = log_sigmoid_fast(s[0]);
        #pragma unroll
        for (int k = 0; k < NEG; k++)
            acc += log_sigmoid_fast(-s[1 + k]);
        out[e] = -acc;
    }
}

extern "C" void kernel_launch(void* const* d_in, const int* in_sizes, int n_in,
                              void* d_out, int out_size)
{
    const float* in_embed  = (const float*)d_in[0];
    const float* out_embed = (const float*)d_in[1];
    const int*   context   = (const int*)d_in[2];
    const int*   target    = (const int*)d_in[3];
    const int*   negatives = (const int*)d_in[4];
    float*       out       = (float*)d_out;

    const int B = out_size;                       // 16384
    const int warps = (B + 1) / 2;                // 2 elements per warp
    const int threads = 128;                      // 4 warps/block
    const int blocks = (warps * 32 + threads - 1) / threads;   // 2048
    cbow_neg_kernel<<<blocks, threads>>>(in_embed, out_embed, context, target,
                                         negatives, out, B);
}